// round 8
// baseline (speedup 1.0000x reference)
#include <cuda_runtime.h>
#include <cstdint>
#include <math.h>
#include <math_constants.h>

#define DIMS 32
#define NCAP 500000
#define TPB  256
#define MSLOTS 1024

// ---- static device scratch (no allocations allowed) ----
__device__ float2 g_xs[(size_t)DIMS * NCAP];          // transposed interleaved {x,s}: [k][j]
__device__ float  g_obj[NCAP];
__device__ float  g_wlp[NCAP];
__device__ unsigned long long g_amin[MSLOTS];          // per-step argmin key (atomicMin)
__device__ unsigned g_cnt[MSLOTS];                     // per-step barrier counters
__device__ float  g_ell2v;

// float -> order-preserving uint32
__device__ __forceinline__ unsigned f2ord(float f) {
    unsigned b = __float_as_uint(f);
    return (b & 0x80000000u) ? ~b : (b | 0x80000000u);
}

__global__ void k_setup(const unsigned* s0, const unsigned* s1) {
    for (int i = 0; i < MSLOTS; i++) { g_amin[i] = 0xFFFFFFFFFFFFFFFFull; g_cnt[i] = 0u; }
    float ell = 1.0f;
    unsigned u0 = s0 ? s0[0] : 0u;
    unsigned u1 = s1 ? s1[0] : 0u;
    unsigned e0 = (u0 >> 23) & 0xffu;
    unsigned e1 = (u1 >> 23) & 0xffu;
    if (e0 >= 64u && e0 <= 191u)      ell = __uint_as_float(u0);
    else if (e1 >= 64u && e1 <= 191u) ell = __uint_as_float(u1);
    float e2 = __fmul_rn(ell, ell);
    if (!(e2 > 1e-20f) || !(e2 < 1e20f)) e2 = 1.0f;
    g_ell2v = e2;
}

__global__ void __launch_bounds__(256) k_transpose(const float4* __restrict__ x4,
                                                   const float4* __restrict__ s4,
                                                   int n) {
    int j = blockIdx.x * blockDim.x + threadIdx.x;
    if (j >= n) return;
#pragma unroll
    for (int i = 0; i < DIMS / 4; i++) {
        float4 xv = x4[(size_t)j * (DIMS / 4) + i];
        float4 sv = s4[(size_t)j * (DIMS / 4) + i];
        g_xs[(size_t)(4 * i + 0) * n + j] = make_float2(xv.x, sv.x);
        g_xs[(size_t)(4 * i + 1) * n + j] = make_float2(xv.y, sv.y);
        g_xs[(size_t)(4 * i + 2) * n + j] = make_float2(xv.z, sv.z);
        g_xs[(size_t)(4 * i + 3) * n + j] = make_float2(xv.w, sv.w);
    }
}

__device__ __forceinline__ void argmin2(float& v, int& i, float v2, int i2) {
    if (v2 < v || (v2 == v && i2 < i)) { v = v2; i = i2; }
}

template <int NT>
__device__ __forceinline__ void block_argmin(float& v, int& i, float* rv, int* ri, int tid) {
#pragma unroll
    for (int off = 16; off > 0; off >>= 1) {
        float v2 = __shfl_down_sync(0xffffffffu, v, off);
        int   i2 = __shfl_down_sync(0xffffffffu, i, off);
        argmin2(v, i, v2, i2);
    }
    if ((tid & 31) == 0) { rv[tid >> 5] = v; ri[tid >> 5] = i; }
    __syncthreads();
    if (tid < 32) {
        const int nw = NT >> 5;
        float vv = (tid < nw) ? rv[tid] : CUDART_INF_F;
        int   ii = (tid < nw) ? ri[tid] : 0x7fffffff;
#pragma unroll
        for (int off = 16; off > 0; off >>= 1) {
            float v2 = __shfl_down_sync(0xffffffffu, vv, off);
            int   i2 = __shfl_down_sync(0xffffffffu, ii, off);
            argmin2(vv, ii, v2, i2);
        }
        if (tid == 0) { rv[0] = vv; ri[0] = ii; }
    }
    __syncthreads();
    v = rv[0]; i = ri[0];
}

// XLA row-reduce tree over 32 elements: pair offsets 16,8,4,2,1
__device__ __forceinline__ float tree16(float* p) {
#pragma unroll
    for (int k = 0; k < 8; k++) p[k] = __fadd_rn(p[k], p[k + 8]);
#pragma unroll
    for (int k = 0; k < 4; k++) p[k] = __fadd_rn(p[k], p[k + 4]);
    p[0] = __fadd_rn(p[0], p[2]); p[1] = __fadd_rn(p[1], p[3]);
    return __fadd_rn(p[0], p[1]);
}

// Per-step cross-SM exchange: atomicMin + counter-barrier (pure L2 atomics).
__device__ __forceinline__ int step_exchange(int t, float bv, int bi, int tid, int nb) {
    __shared__ unsigned long long key_sh;
    if (tid == 0) {
        unsigned long long key = ((unsigned long long)f2ord(bv) << 32) | (unsigned)bi;
        atomicMin(&g_amin[t], key);
        __threadfence();
        atomicAdd(&g_cnt[t], 1u);
        long spins = 0;
        while (atomicAdd(&g_cnt[t], 0u) < (unsigned)nb) {
            __nanosleep(64);
            if (++spins > 2000000L) break;
        }
        key_sh = atomicAdd(&g_amin[t], 0ull);
    }
    __syncthreads();
    return (int)(unsigned)(key_sh & 0xffffffffull);
}

// ---- persistent kernel: whole greedy loop ----
__global__ void __launch_bounds__(TPB) k_stein_pers(
    const float* __restrict__ x, const float* __restrict__ logp,
    const float* __restrict__ sp, const float* __restrict__ lap,
    float* __restrict__ out, int nb, int n, int m) {
    const int tid = threadIdx.x;
    const int bid = blockIdx.x;
    float ell2 = g_ell2v;
    if (!(ell2 > 1e-20f) || !(ell2 < 1e20f)) ell2 = 1.0f;
    const float e4 = __fmul_rn(ell2, ell2);
    const float w = __fdiv_rn(1.0f, (float)m);
    const float dterm = __fdiv_rn((float)DIMS, ell2);

    __shared__ float piv[2 * DIMS];
    __shared__ float rv_sh[TPB / 32];
    __shared__ int   ri_sh[TPB / 32];

    const int per = (n + nb - 1) / nb;
    const int j0  = bid * per;
    const int j1  = min(n, j0 + per);

    // ---- step 0: obj0 = (d/ell2 + tree_sum(s*s)) + laplace - w*log_p ----
    {
        float bv = CUDART_INF_F; int bi = 0x7fffffff;
        const float4* s4 = (const float4*)sp;
        for (int j = j0 + tid; j < j1; j += TPB) {
            float sv[DIMS];
            const float4* row = s4 + (size_t)j * (DIMS / 4);
#pragma unroll
            for (int i = 0; i < DIMS / 4; i++) {
                float4 v = row[i];
                sv[4 * i] = v.x; sv[4 * i + 1] = v.y; sv[4 * i + 2] = v.z; sv[4 * i + 3] = v.w;
            }
            float p[16];
#pragma unroll
            for (int k = 0; k < 16; k++)
                p[k] = __fadd_rn(__fmul_rn(sv[k], sv[k]), __fmul_rn(sv[k + 16], sv[k + 16]));
            float s2 = tree16(p);
            float wl = __fmul_rn(w, logp[j]);
            g_wlp[j] = wl;
            float o = __fsub_rn(__fadd_rn(__fadd_rn(dterm, s2), lap[j]), wl);
            g_obj[j] = o;
            argmin2(bv, bi, o, j);
        }
        block_argmin<TPB>(bv, bi, rv_sh, ri_sh, tid);
        int idx = step_exchange(0, bv, bi, tid, nb);
        if (bid == 0 && tid == 0) out[0] = (float)idx;   // OUTPUT IS FLOAT32
        if (tid < 2 * DIMS)
            piv[tid] = (tid < DIMS) ? x[(size_t)idx * DIMS + tid]
                                    : sp[(size_t)idx * DIMS + (tid - DIMS)];
        __syncthreads();
    }

    // ---- steps 1..m-1 ----
    for (int t = 1; t < m; t++) {
        float bv = CUDART_INF_F; int bi = 0x7fffffff;
        for (int j = j0 + tid; j < j1; j += TPB) {
            float r2p[16], ap[16], bp[16], cp[16];
            const float2* p0 = g_xs + j;
#pragma unroll
            for (int k = 0; k < 16; k++) {
                float2 v0 = __ldcs(&p0[(size_t)k * n]);
                float2 v1 = __ldcs(&p0[(size_t)(k + 16) * n]);
                float xk0 = piv[k],      sk0 = piv[DIMS + k];
                float xk1 = piv[k + 16], sk1 = piv[DIMS + k + 16];
                float d0 = __fsub_rn(xk0, v0.x);
                float d1 = __fsub_rn(xk1, v1.x);
                r2p[k] = __fadd_rn(__fmul_rn(d0, d0),   __fmul_rn(d1, d1));
                ap[k]  = __fadd_rn(__fmul_rn(d0, sk0),  __fmul_rn(d1, sk1));
                bp[k]  = __fadd_rn(__fmul_rn(v0.y, d0), __fmul_rn(v1.y, d1));
                cp[k]  = __fadd_rn(__fmul_rn(v0.y, sk0),__fmul_rn(v1.y, sk1));
            }
            float r2   = tree16(r2p);
            float a    = tree16(ap);
            float b    = tree16(bp);
            float sdot = tree16(cp);

            float q    = __fadd_rn(1.0f, __fdiv_rn(r2, ell2));
            float g    = powf(q, -1.5f);
            float p25  = powf(q, -2.5f);
            float rq   = rsqrtf(q);
            float cross = __fdiv_rn(__fsub_rn(a, b), ell2);
            float t1 = __fmul_rn(dterm, g);
            float t2 = __fmul_rn(__fdiv_rn(__fmul_rn(3.0f, r2), e4), p25);
            float t3 = __fmul_rn(cross, g);
            float t4 = __fmul_rn(sdot, rq);
            float ki = __fadd_rn(__fadd_rn(__fsub_rn(t1, t2), t3), t4);
            float o  = __fsub_rn(__fadd_rn(g_obj[j], __fmul_rn(2.0f, ki)), g_wlp[j]);
            g_obj[j] = o;
            argmin2(bv, bi, o, j);
        }
        block_argmin<TPB>(bv, bi, rv_sh, ri_sh, tid);
        int idx = step_exchange(t, bv, bi, tid, nb);
        if (bid == 0 && tid == 0) out[t] = (float)idx;   // OUTPUT IS FLOAT32
        __syncthreads();
        if (tid < 2 * DIMS)
            piv[tid] = (tid < DIMS) ? x[(size_t)idx * DIMS + tid]
                                    : sp[(size_t)idx * DIMS + (tid - DIMS)];
        __syncthreads();
    }
}

extern "C" void kernel_launch(void* const* d_in, const int* in_sizes, int n_in,
                              void* d_out, int out_size) {
    // Classify inputs by element count; within each size class keep slot order.
    long maxsz = 0;
    for (int i = 0; i < n_in; i++) if ((long)in_sizes[i] > maxsz) maxsz = (long)in_sizes[i];
    long nsz = maxsz;
    for (int i = 0; i < n_in; i++) {
        long s = (long)in_sizes[i];
        if (s > 2 && s < nsz) nsz = s;
    }
    int N = (int)nsz;
    const float *x = nullptr, *sp = nullptr, *logp = nullptr, *lap = nullptr;
    const unsigned *s0 = nullptr, *s1 = nullptr;
    for (int i = 0; i < n_in; i++) {
        long s = (long)in_sizes[i];
        if (s == maxsz && s > 2) {
            if (!x) x = (const float*)d_in[i];
            else if (!sp) sp = (const float*)d_in[i];
        } else if (s == nsz && s > 2 && s != maxsz) {
            if (!logp) logp = (const float*)d_in[i];
            else if (!lap) lap = (const float*)d_in[i];
        } else if (s <= 2) {
            if (!s0) s0 = (const unsigned*)d_in[i];
            else if (!s1) s1 = (const unsigned*)d_in[i];
        }
    }
    if (!logp) { logp = x; lap = sp; }

    float* out = (float*)d_out;   // harness __output__ dtype: float32
    int m = out_size;
    if (m > MSLOTS) m = MSLOTS;

    int dev = 0;
    cudaGetDevice(&dev);
    int sms = 148;
    cudaDeviceGetAttribute(&sms, cudaDevAttrMultiProcessorCount, dev);
    int occ = 1;
    cudaOccupancyMaxActiveBlocksPerMultiprocessor(&occ, k_stein_pers, TPB, 0);
    if (occ < 1) occ = 1;
    long nb_l = (long)sms * occ;
    int nb = (nb_l > 1024) ? 1024 : (int)nb_l;   // co-resident per occupancy API

    k_setup<<<1, 1>>>(s0, s1);
    k_transpose<<<(N + 255) / 256, 256>>>((const float4*)x, (const float4*)sp, N);
    k_stein_pers<<<nb, TPB>>>(x, logp, sp, lap, out, nb, N, m);
}